// round 13
// baseline (speedup 1.0000x reference)
#include <cuda_runtime.h>

// ODEINDLayer: 256 independent SPD block-tridiagonal systems (100 blocks of
// 3x3). SUBSTRUCTURING + SHUFFLE-PCR, one warp per system, ZERO barriers,
// ZERO shared memory:
//   - thread p owns nodes 4p..4p+3; node 4p is an interface node
//   - 3 interior nodes eliminated exactly per-thread (register block-Thomas),
//     storing Za=E^-1 Ga, Zc=E^-1 Gc, zb=E^-1 b for back-substitution
//   - reduced 25-interface block-tridiag solved by 5 PCR levels over
//     __shfl_sync (lanes 0..24 active)
//   - interiors recovered by x = zb - Za*xa - Zc*xc

#define NSYS 256
#define FM 0xffffffffu

__device__ __forceinline__ float frcp_nr(float x) {
    float r; asm("rcp.approx.f32 %0, %1;" : "=f"(r) : "f"(x));
    return r * (2.0f - x * r);
}

// sym 3x3 packed (00,01,02,11,12,22)
__device__ __forceinline__ void inv3(const float M[6], float I[6]) {
    float A00 = M[3]*M[5] - M[4]*M[4];
    float A01 = M[2]*M[4] - M[1]*M[5];
    float A02 = M[1]*M[4] - M[2]*M[3];
    float A11 = M[0]*M[5] - M[2]*M[2];
    float A12 = M[1]*M[2] - M[0]*M[4];
    float A22 = M[0]*M[3] - M[1]*M[1];
    float id  = frcp_nr(M[0]*A00 + M[1]*A01 + M[2]*A02);
    I[0]=A00*id; I[1]=A01*id; I[2]=A02*id; I[3]=A11*id; I[4]=A12*id; I[5]=A22*id;
}
// R = S * M (S sym6, M 3x3 row-major)
__device__ __forceinline__ void smm(const float S[6], const float M[9], float R[9]) {
    R[0]=S[0]*M[0]+S[1]*M[3]+S[2]*M[6]; R[1]=S[0]*M[1]+S[1]*M[4]+S[2]*M[7]; R[2]=S[0]*M[2]+S[1]*M[5]+S[2]*M[8];
    R[3]=S[1]*M[0]+S[3]*M[3]+S[4]*M[6]; R[4]=S[1]*M[1]+S[3]*M[4]+S[4]*M[7]; R[5]=S[1]*M[2]+S[3]*M[5]+S[4]*M[8];
    R[6]=S[2]*M[0]+S[4]*M[3]+S[5]*M[6]; R[7]=S[2]*M[1]+S[4]*M[4]+S[5]*M[7]; R[8]=S[2]*M[2]+S[4]*M[5]+S[5]*M[8];
}
// R = S * M^T
__device__ __forceinline__ void smmT(const float S[6], const float M[9], float R[9]) {
    R[0]=S[0]*M[0]+S[1]*M[1]+S[2]*M[2]; R[1]=S[0]*M[3]+S[1]*M[4]+S[2]*M[5]; R[2]=S[0]*M[6]+S[1]*M[7]+S[2]*M[8];
    R[3]=S[1]*M[0]+S[3]*M[1]+S[4]*M[2]; R[4]=S[1]*M[3]+S[3]*M[4]+S[4]*M[5]; R[5]=S[1]*M[6]+S[3]*M[7]+S[4]*M[8];
    R[6]=S[2]*M[0]+S[4]*M[1]+S[5]*M[2]; R[7]=S[2]*M[3]+S[4]*M[4]+S[5]*M[5]; R[8]=S[2]*M[6]+S[4]*M[7]+S[5]*M[8];
}
// R = A^T * B
__device__ __forceinline__ void mTm(const float A[9], const float B[9], float R[9]) {
    R[0]=A[0]*B[0]+A[3]*B[3]+A[6]*B[6]; R[1]=A[0]*B[1]+A[3]*B[4]+A[6]*B[7]; R[2]=A[0]*B[2]+A[3]*B[5]+A[6]*B[8];
    R[3]=A[1]*B[0]+A[4]*B[3]+A[7]*B[6]; R[4]=A[1]*B[1]+A[4]*B[4]+A[7]*B[7]; R[5]=A[1]*B[2]+A[4]*B[5]+A[7]*B[8];
    R[6]=A[2]*B[0]+A[5]*B[3]+A[8]*B[6]; R[7]=A[2]*B[1]+A[5]*B[4]+A[8]*B[7]; R[8]=A[2]*B[2]+A[5]*B[5]+A[8]*B[8];
}
// R = A * B
__device__ __forceinline__ void mm(const float A[9], const float B[9], float R[9]) {
    R[0]=A[0]*B[0]+A[1]*B[3]+A[2]*B[6]; R[1]=A[0]*B[1]+A[1]*B[4]+A[2]*B[7]; R[2]=A[0]*B[2]+A[1]*B[5]+A[2]*B[8];
    R[3]=A[3]*B[0]+A[4]*B[3]+A[5]*B[6]; R[4]=A[3]*B[1]+A[4]*B[4]+A[5]*B[7]; R[5]=A[3]*B[2]+A[4]*B[5]+A[5]*B[8];
    R[6]=A[6]*B[0]+A[7]*B[3]+A[8]*B[6]; R[7]=A[6]*B[1]+A[7]*B[4]+A[8]*B[7]; R[8]=A[6]*B[2]+A[7]*B[5]+A[8]*B[8];
}
__device__ __forceinline__ void smv(const float S[6], const float v[3], float r[3]) {
    r[0]=S[0]*v[0]+S[1]*v[1]+S[2]*v[2];
    r[1]=S[1]*v[0]+S[3]*v[1]+S[4]*v[2];
    r[2]=S[2]*v[0]+S[4]*v[1]+S[5]*v[2];
}
__device__ __forceinline__ void mTv(const float A[9], const float v[3], float r[3]) {
    r[0]=A[0]*v[0]+A[3]*v[1]+A[6]*v[2];
    r[1]=A[1]*v[0]+A[4]*v[1]+A[7]*v[2];
    r[2]=A[2]*v[0]+A[5]*v[1]+A[8]*v[2];
}
__device__ __forceinline__ void mv(const float A[9], const float v[3], float r[3]) {
    r[0]=A[0]*v[0]+A[1]*v[1]+A[2]*v[2];
    r[1]=A[3]*v[0]+A[4]*v[1]+A[5]*v[2];
    r[2]=A[6]*v[0]+A[7]*v[1]+A[8]*v[2];
}

__device__ __forceinline__ void build(float c0, float c1, float c2, float rt,
        float h, float g, bool first, bool hasU, bool hasL, float iv0, float iv1,
        float D[6], float U[9], float B[3])
{
    D[0]=c0*c0; D[1]=c0*c1; D[2]=c0*c2; D[3]=c1*c1; D[4]=c1*c2; D[5]=c2*c2;
    B[0]=c0*rt; B[1]=c1*rt; B[2]=c2*rt;
    if (first) { D[0]+=1.0f; D[3]+=1.0f; B[0]+=iv0; B[1]+=iv1; }
    if (hasU) {
        float h2=h*h;
        D[0]+=2.0f;      D[1]+=h;                D[2]+=0.5f*h2;
        D[3]+=h2+3.0f;   D[4]+=h*(0.5f*h2+1.5f); D[5]+=h2*(0.25f*h2+1.25f);
        U[0]=-2.0f;    U[1]=h;       U[2]=-0.5f*h2;
        U[3]=-h;       U[4]=-3.0f;   U[5]=1.5f*h;
        U[6]=-0.5f*h2; U[7]=-1.5f*h; U[8]=0.25f*h2;
    } else {
        #pragma unroll
        for (int k = 0; k < 9; ++k) U[k] = 0.0f;
    }
    if (hasL) {
        float g2=g*g;
        D[0]+=2.0f;      D[1]-=g;                D[2]+=0.5f*g2;
        D[3]+=g2+3.0f;   D[4]-=g*(0.5f*g2+1.5f); D[5]+=g2*(0.25f*g2+1.25f);
    }
}

// PCR applies (neighbor pre-inverted)
__device__ __forceinline__ void apply_left(float D[6], float B[3],
        const float I[6], const float Uj[9], const float Bj[3])
{
    float T[9]; smm(I, Uj, T);
    D[0] -= Uj[0]*T[0] + Uj[3]*T[3] + Uj[6]*T[6];
    D[1] -= Uj[0]*T[1] + Uj[3]*T[4] + Uj[6]*T[7];
    D[2] -= Uj[0]*T[2] + Uj[3]*T[5] + Uj[6]*T[8];
    D[3] -= Uj[1]*T[1] + Uj[4]*T[4] + Uj[7]*T[7];
    D[4] -= Uj[1]*T[2] + Uj[4]*T[5] + Uj[7]*T[8];
    D[5] -= Uj[2]*T[2] + Uj[5]*T[5] + Uj[8]*T[8];
    float v[3]; smv(I, Bj, v);
    B[0] -= Uj[0]*v[0] + Uj[3]*v[1] + Uj[6]*v[2];
    B[1] -= Uj[1]*v[0] + Uj[4]*v[1] + Uj[7]*v[2];
    B[2] -= Uj[2]*v[0] + Uj[5]*v[1] + Uj[8]*v[2];
}

__device__ __forceinline__ void apply_right(float D[6], float U[9], float B[3],
        const float I[6], const float Uj[9], const float Bj[3], bool newU)
{
    // P = U * I (I sym)
    float P[9];
    P[0]=U[0]*I[0]+U[1]*I[1]+U[2]*I[2]; P[1]=U[0]*I[1]+U[1]*I[3]+U[2]*I[4]; P[2]=U[0]*I[2]+U[1]*I[4]+U[2]*I[5];
    P[3]=U[3]*I[0]+U[4]*I[1]+U[5]*I[2]; P[4]=U[3]*I[1]+U[4]*I[3]+U[5]*I[4]; P[5]=U[3]*I[2]+U[4]*I[4]+U[5]*I[5];
    P[6]=U[6]*I[0]+U[7]*I[1]+U[8]*I[2]; P[7]=U[6]*I[1]+U[7]*I[3]+U[8]*I[4]; P[8]=U[6]*I[2]+U[7]*I[4]+U[8]*I[5];
    D[0] -= P[0]*U[0] + P[1]*U[1] + P[2]*U[2];
    D[1] -= P[0]*U[3] + P[1]*U[4] + P[2]*U[5];
    D[2] -= P[0]*U[6] + P[1]*U[7] + P[2]*U[8];
    D[3] -= P[3]*U[3] + P[4]*U[4] + P[5]*U[5];
    D[4] -= P[3]*U[6] + P[4]*U[7] + P[5]*U[8];
    D[5] -= P[6]*U[6] + P[7]*U[7] + P[8]*U[8];
    B[0] -= P[0]*Bj[0] + P[1]*Bj[1] + P[2]*Bj[2];
    B[1] -= P[3]*Bj[0] + P[4]*Bj[1] + P[5]*Bj[2];
    B[2] -= P[6]*Bj[0] + P[7]*Bj[1] + P[8]*Bj[2];
    if (newU) {
        float N[9]; mm(P, Uj, N);
        #pragma unroll
        for (int k = 0; k < 9; ++k) U[k] = -N[k];
    }
}

__global__ __launch_bounds__(32)
void ode_sub_kernel(const float* __restrict__ coeffs,
                    const float* __restrict__ rhs,
                    const float* __restrict__ iv_rhs,
                    const float* __restrict__ steps,
                    float* __restrict__ out)
{
    const int sys = blockIdx.x;
    const int p   = threadIdx.x;          // lanes 0..24 own interfaces; 25..31 replicate lane 24
    const int pc  = p < 24 ? p : 24;

    // -------- loads (lanes 25-31 replicate lane 24: no OOB, finite data) --------
    const float4* C4 = reinterpret_cast<const float4*>(coeffs + sys*300 + 12*pc);
    float4 ca = C4[0], cb = C4[1], cc = C4[2];
    float4 rr = *reinterpret_cast<const float4*>(rhs + sys*100 + 4*pc);
    const float* ST = steps + sys*99;
    float h0 = ST[4*pc+0], h1 = ST[4*pc+1], h2 = ST[4*pc+2];
    float h3 = (pc < 24) ? ST[4*pc+3] : 0.0f;
    float hm1 = __shfl_up_sync(FM, h3, 1);   // ST[4p-1]; lane 0 unused
    float iv0 = 0.0f, iv1 = 0.0f;
    if (p == 0) { iv0 = iv_rhs[sys*2]; iv1 = iv_rhs[sys*2+1]; }

    // -------- build interface a=4p and interiors i1..i3 --------
    float Da[6], Ua[9], Ba[3];
    float D1[6], U1[9], b1[3];
    float D2[6], U2[9], b2[3];
    float D3[6], U3[9], b3[3];
    build(ca.x,ca.y,ca.z, rr.x, h0, hm1, p==0, true,   pc>=1, iv0,iv1, Da,Ua,Ba);
    build(ca.w,cb.x,cb.y, rr.y, h1, h0,  false, true,  true,  0,0,     D1,U1,b1);
    build(cb.z,cb.w,cc.x, rr.z, h2, h1,  false, true,  true,  0,0,     D2,U2,b2);
    build(cc.y,cc.z,cc.w, rr.w, h3, h2,  false, pc<24, true,  0,0,     D3,U3,b3);

    // -------- interior block-Thomas factor + multi-RHS solve (registers) --------
    float F1[6]; inv3(D1, F1);
    float y1a[9]; smmT(F1, Ua, y1a);              // F1 * Ua^T
    float y1b[3]; smv(F1, b1, y1b);
    float T1[9];  smm(F1, U1, T1);

    float W[9], t3[3];
    mTm(U1, T1, W);
    float S2[6] = {D2[0]-W[0], D2[1]-W[1], D2[2]-W[2], D2[3]-W[4], D2[4]-W[5], D2[5]-W[8]};
    float F2[6]; inv3(S2, F2);
    mTm(U1, y1a, W);
    float y2a[9]; smm(F2, W, y2a);
    #pragma unroll
    for (int k = 0; k < 9; ++k) y2a[k] = -y2a[k];
    mTv(U1, y1b, t3);
    float tb[3] = {b2[0]-t3[0], b2[1]-t3[1], b2[2]-t3[2]};
    float y2b[3]; smv(F2, tb, y2b);
    float T2[9]; smm(F2, U2, T2);

    mTm(U2, T2, W);
    float S3[6] = {D3[0]-W[0], D3[1]-W[1], D3[2]-W[2], D3[3]-W[4], D3[4]-W[5], D3[5]-W[8]};
    float F3[6]; inv3(S3, F3);
    mTm(U2, y2a, W);
    float Za3[9]; smm(F3, W, Za3);
    #pragma unroll
    for (int k = 0; k < 9; ++k) Za3[k] = -Za3[k];
    float Zc3[9]; smm(F3, U3, Zc3);
    mTv(U2, y2b, t3);
    tb[0]=b3[0]-t3[0]; tb[1]=b3[1]-t3[1]; tb[2]=b3[2]-t3[2];
    float zb3[3]; smv(F3, tb, zb3);

    // back-substitution of the operator columns
    float Za2[9], Zc2[9], zb2[3];
    mm(T2, Za3, W);
    #pragma unroll
    for (int k = 0; k < 9; ++k) Za2[k] = y2a[k] - W[k];
    mm(T2, Zc3, W);
    #pragma unroll
    for (int k = 0; k < 9; ++k) Zc2[k] = -W[k];
    mv(T2, zb3, t3);
    zb2[0]=y2b[0]-t3[0]; zb2[1]=y2b[1]-t3[1]; zb2[2]=y2b[2]-t3[2];

    float Za1[9], Zc1[9], zb1[3];
    mm(T1, Za2, W);
    #pragma unroll
    for (int k = 0; k < 9; ++k) Za1[k] = y1a[k] - W[k];
    mm(T1, Zc2, W);
    #pragma unroll
    for (int k = 0; k < 9; ++k) Zc1[k] = -W[k];
    mv(T1, zb2, t3);
    zb1[0]=y1b[0]-t3[0]; zb1[1]=y1b[1]-t3[1]; zb1[2]=y1b[2]-t3[2];

    // -------- interface equation assembly --------
    float Dh[6], Uh[9], Bh[3];
    mm(Ua, Za1, W);
    Dh[0]=Da[0]-W[0]; Dh[1]=Da[1]-W[1]; Dh[2]=Da[2]-W[2];
    Dh[3]=Da[3]-W[4]; Dh[4]=Da[4]-W[5]; Dh[5]=Da[5]-W[8];
    mm(Ua, Zc1, W);
    #pragma unroll
    for (int k = 0; k < 9; ++k) Uh[k] = -W[k];
    mv(Ua, zb1, t3);
    Bh[0]=Ba[0]-t3[0]; Bh[1]=Ba[1]-t3[1]; Bh[2]=Ba[2]-t3[2];

    // contribution to the NEXT interface (4p+4), shuffled up one lane
    float scd[6], scb[3];
    mTm(U3, Zc3, W);
    scd[0]=-W[0]; scd[1]=-W[1]; scd[2]=-W[2]; scd[3]=-W[4]; scd[4]=-W[5]; scd[5]=-W[8];
    mTv(U3, zb3, t3);
    scb[0]=-t3[0]; scb[1]=-t3[1]; scb[2]=-t3[2];
    float rdd[6], rdb[3];
    #pragma unroll
    for (int k = 0; k < 6; ++k) rdd[k] = __shfl_up_sync(FM, scd[k], 1);
    #pragma unroll
    for (int k = 0; k < 3; ++k) rdb[k] = __shfl_up_sync(FM, scb[k], 1);
    if (p >= 1) {
        #pragma unroll
        for (int k = 0; k < 6; ++k) Dh[k] += rdd[k];
        #pragma unroll
        for (int k = 0; k < 3; ++k) Bh[k] += rdb[k];
    }

    // -------- 5 PCR levels over 25 interfaces, pure shuffles --------
    #pragma unroll
    for (int l = 0; l < 5; ++l) {
        const int s = 1 << l;
        float Ih[6]; inv3(Dh, Ih);
        float IL[6], UL[9], BL[3], IR[6], UR[9], BR[3];
        #pragma unroll
        for (int k = 0; k < 6; ++k) { IL[k]=__shfl_sync(FM, Ih[k], p-s); IR[k]=__shfl_sync(FM, Ih[k], p+s); }
        #pragma unroll
        for (int k = 0; k < 9; ++k) { UL[k]=__shfl_sync(FM, Uh[k], p-s); UR[k]=__shfl_sync(FM, Uh[k], p+s); }
        #pragma unroll
        for (int k = 0; k < 3; ++k) { BL[k]=__shfl_sync(FM, Bh[k], p-s); BR[k]=__shfl_sync(FM, Bh[k], p+s); }
        if (p >= s && p <= 24) apply_left(Dh, Bh, IL, UL, BL);
        if (p + s <= 24)       apply_right(Dh, Uh, Bh, IR, UR, BR, p + 2*s <= 24);
    }

    // -------- interface solve + interior back-substitution --------
    float Ih[6]; inv3(Dh, Ih);
    float xa[3]; smv(Ih, Bh, xa);
    float xc[3];
    #pragma unroll
    for (int k = 0; k < 3; ++k) xc[k] = __shfl_down_sync(FM, xa[k], 1);
    if (p >= 24) { xc[0]=0.0f; xc[1]=0.0f; xc[2]=0.0f; }

    float u3v[3], v3v[3], xi1[3], xi2[3], xi3[3];
    mv(Za1, xa, u3v); mv(Zc1, xc, v3v);
    xi1[0]=zb1[0]-u3v[0]-v3v[0]; xi1[1]=zb1[1]-u3v[1]-v3v[1]; xi1[2]=zb1[2]-u3v[2]-v3v[2];
    mv(Za2, xa, u3v); mv(Zc2, xc, v3v);
    xi2[0]=zb2[0]-u3v[0]-v3v[0]; xi2[1]=zb2[1]-u3v[1]-v3v[1]; xi2[2]=zb2[2]-u3v[2]-v3v[2];
    mv(Za3, xa, u3v); mv(Zc3, xc, v3v);
    xi3[0]=zb3[0]-u3v[0]-v3v[0]; xi3[1]=zb3[1]-u3v[1]-v3v[1]; xi3[2]=zb3[2]-u3v[2]-v3v[2];

    // -------- outputs --------
    if (p < 25) {
        const int b0 = sys*100 + 4*p;
        out[b0+0]=xa[0];  out[b0+1]=xi1[0]; out[b0+2]=xi2[0]; out[b0+3]=xi3[0];
        out[25600+b0+0]=xa[1]; out[25600+b0+1]=xi1[1]; out[25600+b0+2]=xi2[1]; out[25600+b0+3]=xi3[1];
        out[51200+b0+0]=xa[2]; out[51200+b0+1]=xi1[2]; out[51200+b0+2]=xi2[2]; out[51200+b0+3]=xi3[2];
        const int sb = 77056 + sys*99 + 4*p;
        out[sb+0]=h0; out[sb+1]=h1; out[sb+2]=h2;
        if (p < 24) out[sb+3]=h3;
        if (p == 0) out[76800 + sys] = 0.0f;
    }
}

extern "C" void kernel_launch(void* const* d_in, const int* in_sizes, int n_in,
                              void* d_out, int out_size)
{
    (void)out_size;
    const float* coeffs = nullptr;
    const float* rhs    = nullptr;
    const float* iv_rhs = nullptr;
    const float* steps  = nullptr;
    for (int i = 0; i < n_in; ++i) {
        switch (in_sizes[i]) {
            case 76800: coeffs = (const float*)d_in[i]; break;
            case 25600: rhs    = (const float*)d_in[i]; break;
            case 512:   iv_rhs = (const float*)d_in[i]; break;
            case 25344: steps  = (const float*)d_in[i]; break;
            default: break;
        }
    }
    if (!coeffs && n_in > 0) coeffs = (const float*)d_in[0];
    if (!rhs    && n_in > 1) rhs    = (const float*)d_in[1];
    if (!iv_rhs && n_in > 2) iv_rhs = (const float*)d_in[2];
    if (!steps  && n_in > 3) steps  = (const float*)d_in[3];

    ode_sub_kernel<<<NSYS, 32>>>(coeffs, rhs, iv_rhs, steps, (float*)d_out);
}

// round 14
// speedup vs baseline: 1.0295x; 1.0295x over previous
#include <cuda_runtime.h>

// ODEINDLayer: 256 independent SPD block-tridiagonal systems (100 blocks of
// 3x3). SUBSTRUCTURING + SHUFFLE-PCR, one WARP per system, TWO systems per
// CTA (warps land on different SMSPs -> no scheduler contention), zero
// barriers, zero shared memory.
//   - lane p owns nodes 4p..4p+3; node 4p is an interface node
//   - 3 interior nodes eliminated exactly per-lane (register block-Thomas)
//   - reduced 25-interface block-tridiag solved by 5 shuffle-PCR levels
//   - interiors recovered by x = zb - Za*xa - Zc*xc

#define NSYS 256
#define FM 0xffffffffu

__device__ __forceinline__ float frcp_fast(float x) {
    float r; asm("rcp.approx.f32 %0, %1;" : "=f"(r) : "f"(x));
    return r;
}

// sym 3x3 packed (00,01,02,11,12,22)
__device__ __forceinline__ void inv3(const float M[6], float I[6]) {
    float A00 = M[3]*M[5] - M[4]*M[4];
    float A01 = M[2]*M[4] - M[1]*M[5];
    float A02 = M[1]*M[4] - M[2]*M[3];
    float A11 = M[0]*M[5] - M[2]*M[2];
    float A12 = M[1]*M[2] - M[0]*M[4];
    float A22 = M[0]*M[3] - M[1]*M[1];
    float id  = frcp_fast(M[0]*A00 + M[1]*A01 + M[2]*A02);
    I[0]=A00*id; I[1]=A01*id; I[2]=A02*id; I[3]=A11*id; I[4]=A12*id; I[5]=A22*id;
}
// R = S * M (S sym6, M 3x3 row-major)
__device__ __forceinline__ void smm(const float S[6], const float M[9], float R[9]) {
    R[0]=S[0]*M[0]+S[1]*M[3]+S[2]*M[6]; R[1]=S[0]*M[1]+S[1]*M[4]+S[2]*M[7]; R[2]=S[0]*M[2]+S[1]*M[5]+S[2]*M[8];
    R[3]=S[1]*M[0]+S[3]*M[3]+S[4]*M[6]; R[4]=S[1]*M[1]+S[3]*M[4]+S[4]*M[7]; R[5]=S[1]*M[2]+S[3]*M[5]+S[4]*M[8];
    R[6]=S[2]*M[0]+S[4]*M[3]+S[5]*M[6]; R[7]=S[2]*M[1]+S[4]*M[4]+S[5]*M[7]; R[8]=S[2]*M[2]+S[4]*M[5]+S[5]*M[8];
}
// R = S * M^T
__device__ __forceinline__ void smmT(const float S[6], const float M[9], float R[9]) {
    R[0]=S[0]*M[0]+S[1]*M[1]+S[2]*M[2]; R[1]=S[0]*M[3]+S[1]*M[4]+S[2]*M[5]; R[2]=S[0]*M[6]+S[1]*M[7]+S[2]*M[8];
    R[3]=S[1]*M[0]+S[3]*M[1]+S[4]*M[2]; R[4]=S[1]*M[3]+S[3]*M[4]+S[4]*M[5]; R[5]=S[1]*M[6]+S[3]*M[7]+S[4]*M[8];
    R[6]=S[2]*M[0]+S[4]*M[1]+S[5]*M[2]; R[7]=S[2]*M[3]+S[4]*M[4]+S[5]*M[5]; R[8]=S[2]*M[6]+S[4]*M[7]+S[5]*M[8];
}
// R = A^T * B
__device__ __forceinline__ void mTm(const float A[9], const float B[9], float R[9]) {
    R[0]=A[0]*B[0]+A[3]*B[3]+A[6]*B[6]; R[1]=A[0]*B[1]+A[3]*B[4]+A[6]*B[7]; R[2]=A[0]*B[2]+A[3]*B[5]+A[6]*B[8];
    R[3]=A[1]*B[0]+A[4]*B[3]+A[7]*B[6]; R[4]=A[1]*B[1]+A[4]*B[4]+A[7]*B[7]; R[5]=A[1]*B[2]+A[4]*B[5]+A[7]*B[8];
    R[6]=A[2]*B[0]+A[5]*B[3]+A[8]*B[6]; R[7]=A[2]*B[1]+A[5]*B[4]+A[8]*B[7]; R[8]=A[2]*B[2]+A[5]*B[5]+A[8]*B[8];
}
// R = A * B
__device__ __forceinline__ void mm(const float A[9], const float B[9], float R[9]) {
    R[0]=A[0]*B[0]+A[1]*B[3]+A[2]*B[6]; R[1]=A[0]*B[1]+A[1]*B[4]+A[2]*B[7]; R[2]=A[0]*B[2]+A[1]*B[5]+A[2]*B[8];
    R[3]=A[3]*B[0]+A[4]*B[3]+A[5]*B[6]; R[4]=A[3]*B[1]+A[4]*B[4]+A[5]*B[7]; R[5]=A[3]*B[2]+A[4]*B[5]+A[5]*B[8];
    R[6]=A[6]*B[0]+A[7]*B[3]+A[8]*B[6]; R[7]=A[6]*B[1]+A[7]*B[4]+A[8]*B[7]; R[8]=A[6]*B[2]+A[7]*B[5]+A[8]*B[8];
}
__device__ __forceinline__ void smv(const float S[6], const float v[3], float r[3]) {
    r[0]=S[0]*v[0]+S[1]*v[1]+S[2]*v[2];
    r[1]=S[1]*v[0]+S[3]*v[1]+S[4]*v[2];
    r[2]=S[2]*v[0]+S[4]*v[1]+S[5]*v[2];
}
__device__ __forceinline__ void mTv(const float A[9], const float v[3], float r[3]) {
    r[0]=A[0]*v[0]+A[3]*v[1]+A[6]*v[2];
    r[1]=A[1]*v[0]+A[4]*v[1]+A[7]*v[2];
    r[2]=A[2]*v[0]+A[5]*v[1]+A[8]*v[2];
}
__device__ __forceinline__ void mv(const float A[9], const float v[3], float r[3]) {
    r[0]=A[0]*v[0]+A[1]*v[1]+A[2]*v[2];
    r[1]=A[3]*v[0]+A[4]*v[1]+A[5]*v[2];
    r[2]=A[6]*v[0]+A[7]*v[1]+A[8]*v[2];
}

__device__ __forceinline__ void build(float c0, float c1, float c2, float rt,
        float h, float g, bool first, bool hasU, bool hasL, float iv0, float iv1,
        float D[6], float U[9], float B[3])
{
    D[0]=c0*c0; D[1]=c0*c1; D[2]=c0*c2; D[3]=c1*c1; D[4]=c1*c2; D[5]=c2*c2;
    B[0]=c0*rt; B[1]=c1*rt; B[2]=c2*rt;
    if (first) { D[0]+=1.0f; D[3]+=1.0f; B[0]+=iv0; B[1]+=iv1; }
    if (hasU) {
        float h2=h*h;
        D[0]+=2.0f;      D[1]+=h;                D[2]+=0.5f*h2;
        D[3]+=h2+3.0f;   D[4]+=h*(0.5f*h2+1.5f); D[5]+=h2*(0.25f*h2+1.25f);
        U[0]=-2.0f;    U[1]=h;       U[2]=-0.5f*h2;
        U[3]=-h;       U[4]=-3.0f;   U[5]=1.5f*h;
        U[6]=-0.5f*h2; U[7]=-1.5f*h; U[8]=0.25f*h2;
    } else {
        #pragma unroll
        for (int k = 0; k < 9; ++k) U[k] = 0.0f;
    }
    if (hasL) {
        float g2=g*g;
        D[0]+=2.0f;      D[1]-=g;                D[2]+=0.5f*g2;
        D[3]+=g2+3.0f;   D[4]-=g*(0.5f*g2+1.5f); D[5]+=g2*(0.25f*g2+1.25f);
    }
}

__device__ __forceinline__ void apply_left(float D[6], float B[3],
        const float I[6], const float Uj[9], const float Bj[3])
{
    float T[9]; smm(I, Uj, T);
    D[0] -= Uj[0]*T[0] + Uj[3]*T[3] + Uj[6]*T[6];
    D[1] -= Uj[0]*T[1] + Uj[3]*T[4] + Uj[6]*T[7];
    D[2] -= Uj[0]*T[2] + Uj[3]*T[5] + Uj[6]*T[8];
    D[3] -= Uj[1]*T[1] + Uj[4]*T[4] + Uj[7]*T[7];
    D[4] -= Uj[1]*T[2] + Uj[4]*T[5] + Uj[7]*T[8];
    D[5] -= Uj[2]*T[2] + Uj[5]*T[5] + Uj[8]*T[8];
    float v[3]; smv(I, Bj, v);
    B[0] -= Uj[0]*v[0] + Uj[3]*v[1] + Uj[6]*v[2];
    B[1] -= Uj[1]*v[0] + Uj[4]*v[1] + Uj[7]*v[2];
    B[2] -= Uj[2]*v[0] + Uj[5]*v[1] + Uj[8]*v[2];
}

__device__ __forceinline__ void apply_right(float D[6], float U[9], float B[3],
        const float I[6], const float Uj[9], const float Bj[3], bool newU)
{
    float P[9];
    P[0]=U[0]*I[0]+U[1]*I[1]+U[2]*I[2]; P[1]=U[0]*I[1]+U[1]*I[3]+U[2]*I[4]; P[2]=U[0]*I[2]+U[1]*I[4]+U[2]*I[5];
    P[3]=U[3]*I[0]+U[4]*I[1]+U[5]*I[2]; P[4]=U[3]*I[1]+U[4]*I[3]+U[5]*I[4]; P[5]=U[3]*I[2]+U[4]*I[4]+U[5]*I[5];
    P[6]=U[6]*I[0]+U[7]*I[1]+U[8]*I[2]; P[7]=U[6]*I[1]+U[7]*I[3]+U[8]*I[4]; P[8]=U[6]*I[2]+U[7]*I[4]+U[8]*I[5];
    D[0] -= P[0]*U[0] + P[1]*U[1] + P[2]*U[2];
    D[1] -= P[0]*U[3] + P[1]*U[4] + P[2]*U[5];
    D[2] -= P[0]*U[6] + P[1]*U[7] + P[2]*U[8];
    D[3] -= P[3]*U[3] + P[4]*U[4] + P[5]*U[5];
    D[4] -= P[3]*U[6] + P[4]*U[7] + P[5]*U[8];
    D[5] -= P[6]*U[6] + P[7]*U[7] + P[8]*U[8];
    B[0] -= P[0]*Bj[0] + P[1]*Bj[1] + P[2]*Bj[2];
    B[1] -= P[3]*Bj[0] + P[4]*Bj[1] + P[5]*Bj[2];
    B[2] -= P[6]*Bj[0] + P[7]*Bj[1] + P[8]*Bj[2];
    if (newU) {
        float N[9]; mm(P, Uj, N);
        #pragma unroll
        for (int k = 0; k < 9; ++k) U[k] = -N[k];
    }
}

__global__ __launch_bounds__(64)
void ode_sub2_kernel(const float* __restrict__ coeffs,
                     const float* __restrict__ rhs,
                     const float* __restrict__ iv_rhs,
                     const float* __restrict__ steps,
                     float* __restrict__ out)
{
    const int sys = blockIdx.x * 2 + (threadIdx.x >> 5);   // one system per warp
    const int p   = threadIdx.x & 31;                      // lane within warp
    const int pc  = p < 24 ? p : 24;

    // -------- loads (lanes 25-31 replicate lane 24) --------
    const float4* C4 = reinterpret_cast<const float4*>(coeffs + sys*300 + 12*pc);
    float4 ca = C4[0], cb = C4[1], cc = C4[2];
    float4 rr = *reinterpret_cast<const float4*>(rhs + sys*100 + 4*pc);
    const float* ST = steps + sys*99;
    float h0 = ST[4*pc+0], h1 = ST[4*pc+1], h2 = ST[4*pc+2];
    float h3 = (pc < 24) ? ST[4*pc+3] : 0.0f;
    float hm1 = __shfl_up_sync(FM, h3, 1);   // ST[4p-1]; lane 0 unused
    float iv0 = 0.0f, iv1 = 0.0f;
    if (p == 0) { iv0 = iv_rhs[sys*2]; iv1 = iv_rhs[sys*2+1]; }

    // -------- build interface a=4p and interiors i1..i3 --------
    float Da[6], Ua[9], Ba[3];
    float D1[6], U1[9], b1[3];
    float D2[6], U2[9], b2[3];
    float D3[6], U3[9], b3[3];
    build(ca.x,ca.y,ca.z, rr.x, h0, hm1, p==0, true,   pc>=1, iv0,iv1, Da,Ua,Ba);
    build(ca.w,cb.x,cb.y, rr.y, h1, h0,  false, true,  true,  0,0,     D1,U1,b1);
    build(cb.z,cb.w,cc.x, rr.z, h2, h1,  false, true,  true,  0,0,     D2,U2,b2);
    build(cc.y,cc.z,cc.w, rr.w, h3, h2,  false, pc<24, true,  0,0,     D3,U3,b3);

    // -------- interior block-Thomas factor + multi-RHS solve (registers) --------
    float F1[6]; inv3(D1, F1);
    float y1a[9]; smmT(F1, Ua, y1a);
    float y1b[3]; smv(F1, b1, y1b);
    float T1[9];  smm(F1, U1, T1);

    float W[9], t3[3];
    mTm(U1, T1, W);
    float S2[6] = {D2[0]-W[0], D2[1]-W[1], D2[2]-W[2], D2[3]-W[4], D2[4]-W[5], D2[5]-W[8]};
    float F2[6]; inv3(S2, F2);
    mTm(U1, y1a, W);
    float y2a[9]; smm(F2, W, y2a);
    #pragma unroll
    for (int k = 0; k < 9; ++k) y2a[k] = -y2a[k];
    mTv(U1, y1b, t3);
    float tb[3] = {b2[0]-t3[0], b2[1]-t3[1], b2[2]-t3[2]};
    float y2b[3]; smv(F2, tb, y2b);
    float T2[9]; smm(F2, U2, T2);

    mTm(U2, T2, W);
    float S3[6] = {D3[0]-W[0], D3[1]-W[1], D3[2]-W[2], D3[3]-W[4], D3[4]-W[5], D3[5]-W[8]};
    float F3[6]; inv3(S3, F3);
    mTm(U2, y2a, W);
    float Za3[9]; smm(F3, W, Za3);
    #pragma unroll
    for (int k = 0; k < 9; ++k) Za3[k] = -Za3[k];
    float Zc3[9]; smm(F3, U3, Zc3);
    mTv(U2, y2b, t3);
    tb[0]=b3[0]-t3[0]; tb[1]=b3[1]-t3[1]; tb[2]=b3[2]-t3[2];
    float zb3[3]; smv(F3, tb, zb3);

    // operator back-substitution
    float Za2[9], Zc2[9], zb2[3];
    mm(T2, Za3, W);
    #pragma unroll
    for (int k = 0; k < 9; ++k) Za2[k] = y2a[k] - W[k];
    mm(T2, Zc3, W);
    #pragma unroll
    for (int k = 0; k < 9; ++k) Zc2[k] = -W[k];
    mv(T2, zb3, t3);
    zb2[0]=y2b[0]-t3[0]; zb2[1]=y2b[1]-t3[1]; zb2[2]=y2b[2]-t3[2];

    float Za1[9], Zc1[9], zb1[3];
    mm(T1, Za2, W);
    #pragma unroll
    for (int k = 0; k < 9; ++k) Za1[k] = y1a[k] - W[k];
    mm(T1, Zc2, W);
    #pragma unroll
    for (int k = 0; k < 9; ++k) Zc1[k] = -W[k];
    mv(T1, zb2, t3);
    zb1[0]=y1b[0]-t3[0]; zb1[1]=y1b[1]-t3[1]; zb1[2]=y1b[2]-t3[2];

    // -------- interface equation assembly --------
    float Dh[6], Uh[9], Bh[3];
    mm(Ua, Za1, W);
    Dh[0]=Da[0]-W[0]; Dh[1]=Da[1]-W[1]; Dh[2]=Da[2]-W[2];
    Dh[3]=Da[3]-W[4]; Dh[4]=Da[4]-W[5]; Dh[5]=Da[5]-W[8];
    mm(Ua, Zc1, W);
    #pragma unroll
    for (int k = 0; k < 9; ++k) Uh[k] = -W[k];
    mv(Ua, zb1, t3);
    Bh[0]=Ba[0]-t3[0]; Bh[1]=Ba[1]-t3[1]; Bh[2]=Ba[2]-t3[2];

    // contribution to the NEXT interface (4p+4), shuffled up one lane
    float scd[6], scb[3];
    mTm(U3, Zc3, W);
    scd[0]=-W[0]; scd[1]=-W[1]; scd[2]=-W[2]; scd[3]=-W[4]; scd[4]=-W[5]; scd[5]=-W[8];
    mTv(U3, zb3, t3);
    scb[0]=-t3[0]; scb[1]=-t3[1]; scb[2]=-t3[2];
    float rdd[6], rdb[3];
    #pragma unroll
    for (int k = 0; k < 6; ++k) rdd[k] = __shfl_up_sync(FM, scd[k], 1);
    #pragma unroll
    for (int k = 0; k < 3; ++k) rdb[k] = __shfl_up_sync(FM, scb[k], 1);
    if (p >= 1) {
        #pragma unroll
        for (int k = 0; k < 6; ++k) Dh[k] += rdd[k];
        #pragma unroll
        for (int k = 0; k < 3; ++k) Bh[k] += rdb[k];
    }

    // -------- 5 PCR levels over 25 interfaces, pure shuffles --------
    #pragma unroll
    for (int l = 0; l < 5; ++l) {
        const int s = 1 << l;
        float Ih[6]; inv3(Dh, Ih);
        float IL[6], UL[9], BL[3], IR[6], UR[9], BR[3];
        #pragma unroll
        for (int k = 0; k < 6; ++k) { IL[k]=__shfl_sync(FM, Ih[k], p-s); IR[k]=__shfl_sync(FM, Ih[k], p+s); }
        #pragma unroll
        for (int k = 0; k < 9; ++k) { UL[k]=__shfl_sync(FM, Uh[k], p-s); UR[k]=__shfl_sync(FM, Uh[k], p+s); }
        #pragma unroll
        for (int k = 0; k < 3; ++k) { BL[k]=__shfl_sync(FM, Bh[k], p-s); BR[k]=__shfl_sync(FM, Bh[k], p+s); }
        if (p >= s && p <= 24) apply_left(Dh, Bh, IL, UL, BL);
        if (p + s <= 24)       apply_right(Dh, Uh, Bh, IR, UR, BR, p + 2*s <= 24);
    }

    // -------- interface solve + interior back-substitution --------
    float Ih[6]; inv3(Dh, Ih);
    float xa[3]; smv(Ih, Bh, xa);
    float xc[3];
    #pragma unroll
    for (int k = 0; k < 3; ++k) xc[k] = __shfl_down_sync(FM, xa[k], 1);
    if (p >= 24) { xc[0]=0.0f; xc[1]=0.0f; xc[2]=0.0f; }

    float u3v[3], v3v[3], xi1[3], xi2[3], xi3[3];
    mv(Za1, xa, u3v); mv(Zc1, xc, v3v);
    xi1[0]=zb1[0]-u3v[0]-v3v[0]; xi1[1]=zb1[1]-u3v[1]-v3v[1]; xi1[2]=zb1[2]-u3v[2]-v3v[2];
    mv(Za2, xa, u3v); mv(Zc2, xc, v3v);
    xi2[0]=zb2[0]-u3v[0]-v3v[0]; xi2[1]=zb2[1]-u3v[1]-v3v[1]; xi2[2]=zb2[2]-u3v[2]-v3v[2];
    mv(Za3, xa, u3v); mv(Zc3, xc, v3v);
    xi3[0]=zb3[0]-u3v[0]-v3v[0]; xi3[1]=zb3[1]-u3v[1]-v3v[1]; xi3[2]=zb3[2]-u3v[2]-v3v[2];

    // -------- outputs --------
    if (p < 25) {
        const int b0 = sys*100 + 4*p;
        out[b0+0]=xa[0];  out[b0+1]=xi1[0]; out[b0+2]=xi2[0]; out[b0+3]=xi3[0];
        out[25600+b0+0]=xa[1]; out[25600+b0+1]=xi1[1]; out[25600+b0+2]=xi2[1]; out[25600+b0+3]=xi3[1];
        out[51200+b0+0]=xa[2]; out[51200+b0+1]=xi1[2]; out[51200+b0+2]=xi2[2]; out[51200+b0+3]=xi3[2];
        const int sb = 77056 + sys*99 + 4*p;
        out[sb+0]=h0; out[sb+1]=h1; out[sb+2]=h2;
        if (p < 24) out[sb+3]=h3;
        if (p == 0) out[76800 + sys] = 0.0f;
    }
}

extern "C" void kernel_launch(void* const* d_in, const int* in_sizes, int n_in,
                              void* d_out, int out_size)
{
    (void)out_size;
    const float* coeffs = nullptr;
    const float* rhs    = nullptr;
    const float* iv_rhs = nullptr;
    const float* steps  = nullptr;
    for (int i = 0; i < n_in; ++i) {
        switch (in_sizes[i]) {
            case 76800: coeffs = (const float*)d_in[i]; break;
            case 25600: rhs    = (const float*)d_in[i]; break;
            case 512:   iv_rhs = (const float*)d_in[i]; break;
            case 25344: steps  = (const float*)d_in[i]; break;
            default: break;
        }
    }
    if (!coeffs && n_in > 0) coeffs = (const float*)d_in[0];
    if (!rhs    && n_in > 1) rhs    = (const float*)d_in[1];
    if (!iv_rhs && n_in > 2) iv_rhs = (const float*)d_in[2];
    if (!steps  && n_in > 3) steps  = (const float*)d_in[3];

    ode_sub2_kernel<<<NSYS/2, 64>>>(coeffs, rhs, iv_rhs, steps, (float*)d_out);
}